// round 15
// baseline (speedup 1.0000x reference)
#include <cuda_runtime.h>

// ---------------------------------------------------------------------------
// Multi-slice ptychography, fused, f32x2-packed, 9-pass schedule.
//  0 R: probe, xT0, conv        5 C: conv, xT5, conv
//  1 C: conv, xT1, conv         6 R: conv, xT6, conv
//  2 R: conv, xT2, conv         7 C: conv, xT7, DIF(det-y)
//  3 C: conv, xT3, conv         8 R: DIF(det-x), |.|^2
//  4 R: conv, xT4, conv
// SMEM pair-packed u64[pair][c]; rows passes use direct LDS.64/STS.64.
// T=exp(iV) precomputed both orientations. Mid-transmit T lines prefetched
// into L1 at pass start so the LDG latency hides under the first FFT block.
// ---------------------------------------------------------------------------

typedef unsigned long long u64;

#define PITCH2 129                       // u64 units per pair-row
#define SMEM_BYTES (2 * 64 * PITCH2 * 8) // 132096
#define RSQRT2 0.70710678118654752440f

static __device__ float  g_int[4u * 256u * 128u * 128u];    // 64 MB scratch
static __device__ float2 g_trow[8u * 512u * 512u];          // 16 MB T row-major
static __device__ float2 g_tcol[8u * 512u * 512u];          // 16 MB T transposed

// ----------------------------- f32x2 helpers --------------------------------
__device__ __forceinline__ u64 pk(float a, float b) {
    u64 r; asm("mov.b64 %0,{%1,%2};" : "=l"(r) : "f"(a), "f"(b)); return r;
}
__device__ __forceinline__ void upk(u64 v, float& a, float& b) {
    asm("mov.b64 {%0,%1},%2;" : "=f"(a), "=f"(b) : "l"(v));
}
__device__ __forceinline__ u64 f2add(u64 a, u64 b) {
    u64 d; asm("add.rn.f32x2 %0,%1,%2;" : "=l"(d) : "l"(a), "l"(b)); return d;
}
__device__ __forceinline__ u64 f2sub(u64 a, u64 b) {
    u64 d; asm("sub.rn.f32x2 %0,%1,%2;" : "=l"(d) : "l"(a), "l"(b)); return d;
}
__device__ __forceinline__ u64 f2mul(u64 a, u64 b) {
    u64 d; asm("mul.rn.f32x2 %0,%1,%2;" : "=l"(d) : "l"(a), "l"(b)); return d;
}
__device__ __forceinline__ u64 f2fma(u64 a, u64 b, u64 c) {
    u64 d; asm("fma.rn.f32x2 %0,%1,%2,%3;" : "=l"(d) : "l"(a), "l"(b), "l"(c)); return d;
}
__device__ __forceinline__ u64 f2neg(u64 v) {
    return v ^ 0x8000000080000000ull;
}
__device__ __forceinline__ u64 shx(u64 v, int s) {
    float a, b; upk(v, a, b);
    a = __shfl_xor_sync(0xffffffffu, a, s);
    b = __shfl_xor_sync(0xffffffffu, b, s);
    return pk(a, b);
}
__device__ __forceinline__ void pref_l1(const void* p) {
    asm volatile("prefetch.global.L1 [%0];" :: "l"(p));
}

__device__ __forceinline__ void cmul_sc(u64& r, u64& i, float tr, float ti) {
    u64 Tr = pk(tr, tr), Ti = pk(ti, ti);
    u64 rr = f2sub(f2mul(r, Tr), f2mul(i, Ti));
    i = f2fma(r, Ti, f2mul(i, Tr));
    r = rr;
}
__device__ __forceinline__ void cmulc_sc(u64& r, u64& i, float tr, float ti) {
    u64 Tr = pk(tr, tr), Ti = pk(ti, ti);
    u64 rr = f2fma(i, Ti, f2mul(r, Tr));
    i = f2sub(f2mul(i, Tr), f2mul(r, Ti));
    r = rr;
}

// ------------------------- twiddle context ----------------------------------
struct Tw4 {
    float owr[8], owi[8];     // outer twiddles W^(l16*t)
    u64 K;
    u64 c8r, c8i, c4r, c4i, c2r, c2i;   // effective cross twiddles (hi lanes)
    u64 sg8, sg4, sg2, sg1;   // butterfly signs
};

__device__ __forceinline__ void cross_dif(u64 (&R)[8], u64 (&I)[8], int s,
                                          u64 sg, u64 cr, u64 ci)
{
    u64 nci = f2neg(ci);
#pragma unroll
    for (int j = 0; j < 8; j++) {
        u64 pR = shx(R[j], s), pI = shx(I[j], s);
        u64 xR = f2fma(sg, R[j], pR);
        u64 xI = f2fma(sg, I[j], pI);
        R[j] = f2fma(xI, nci, f2mul(xR, cr));
        I[j] = f2fma(xI, cr,  f2mul(xR, ci));
    }
}
__device__ __forceinline__ void cross_dit(u64 (&R)[8], u64 (&I)[8], int s,
                                          u64 sg, u64 cr, u64 ci)
{
    u64 nci = f2neg(ci);
#pragma unroll
    for (int j = 0; j < 8; j++) {
        u64 uR = f2fma(I[j], ci,  f2mul(R[j], cr));
        u64 uI = f2fma(R[j], nci, f2mul(I[j], cr));
        u64 pR = shx(uR, s), pI = shx(uI, s);
        R[j] = f2fma(sg, uR, pR);
        I[j] = f2fma(sg, uI, pI);
    }
}

__device__ __forceinline__ void dif8(u64 (&R)[8], u64 (&I)[8], const Tw4& T)
{
    {
        u64 dr, di;
        dr = f2sub(R[0], R[4]);  di = f2sub(I[0], I[4]);
        R[0] = f2add(R[0], R[4]);  I[0] = f2add(I[0], I[4]);
        R[4] = dr;  I[4] = di;
        dr = f2sub(R[1], R[5]);  di = f2sub(I[1], I[5]);
        R[1] = f2add(R[1], R[5]);  I[1] = f2add(I[1], I[5]);
        R[5] = f2mul(f2add(dr, di), T.K);
        I[5] = f2mul(f2sub(di, dr), T.K);
        dr = f2sub(R[2], R[6]);  di = f2sub(I[2], I[6]);
        R[2] = f2add(R[2], R[6]);  I[2] = f2add(I[2], I[6]);
        R[6] = di;  I[6] = f2neg(dr);
        dr = f2sub(R[3], R[7]);  di = f2sub(I[3], I[7]);
        R[3] = f2add(R[3], R[7]);  I[3] = f2add(I[3], I[7]);
        R[7] = f2mul(f2sub(di, dr), T.K);
        I[7] = f2mul(f2neg(f2add(dr, di)), T.K);
    }
    {
        u64 dr, di;
        dr = f2sub(R[0], R[2]);  di = f2sub(I[0], I[2]);
        R[0] = f2add(R[0], R[2]);  I[0] = f2add(I[0], I[2]);
        R[2] = dr;  I[2] = di;
        dr = f2sub(R[4], R[6]);  di = f2sub(I[4], I[6]);
        R[4] = f2add(R[4], R[6]);  I[4] = f2add(I[4], I[6]);
        R[6] = dr;  I[6] = di;
        dr = f2sub(R[1], R[3]);  di = f2sub(I[1], I[3]);
        R[1] = f2add(R[1], R[3]);  I[1] = f2add(I[1], I[3]);
        R[3] = di;  I[3] = f2neg(dr);
        dr = f2sub(R[5], R[7]);  di = f2sub(I[5], I[7]);
        R[5] = f2add(R[5], R[7]);  I[5] = f2add(I[5], I[7]);
        R[7] = di;  I[7] = f2neg(dr);
    }
#pragma unroll
    for (int b = 0; b < 8; b += 2) {
        u64 dr = f2sub(R[b], R[b + 1]), di = f2sub(I[b], I[b + 1]);
        R[b] = f2add(R[b], R[b + 1]);  I[b] = f2add(I[b], I[b + 1]);
        R[b + 1] = dr;  I[b + 1] = di;
    }
    cmul_sc(R[1], I[1], T.owr[4], T.owi[4]);
    cmul_sc(R[2], I[2], T.owr[2], T.owi[2]);
    cmul_sc(R[3], I[3], T.owr[6], T.owi[6]);
    cmul_sc(R[4], I[4], T.owr[1], T.owi[1]);
    cmul_sc(R[5], I[5], T.owr[5], T.owi[5]);
    cmul_sc(R[6], I[6], T.owr[3], T.owi[3]);
    cmul_sc(R[7], I[7], T.owr[7], T.owi[7]);
    cross_dif(R, I, 8, T.sg8, T.c8r, T.c8i);
    cross_dif(R, I, 4, T.sg4, T.c4r, T.c4i);
    cross_dif(R, I, 2, T.sg2, T.c2r, T.c2i);
#pragma unroll
    for (int j = 0; j < 8; j++) {
        u64 pR = shx(R[j], 1), pI = shx(I[j], 1);
        R[j] = f2fma(T.sg1, R[j], pR);
        I[j] = f2fma(T.sg1, I[j], pI);
    }
}

__device__ __forceinline__ void dit8(u64 (&R)[8], u64 (&I)[8], const Tw4& T)
{
#pragma unroll
    for (int j = 0; j < 8; j++) {
        u64 pR = shx(R[j], 1), pI = shx(I[j], 1);
        R[j] = f2fma(T.sg1, R[j], pR);
        I[j] = f2fma(T.sg1, I[j], pI);
    }
    cross_dit(R, I, 2, T.sg2, T.c2r, T.c2i);
    cross_dit(R, I, 4, T.sg4, T.c4r, T.c4i);
    cross_dit(R, I, 8, T.sg8, T.c8r, T.c8i);
    cmulc_sc(R[1], I[1], T.owr[4], T.owi[4]);
    cmulc_sc(R[2], I[2], T.owr[2], T.owi[2]);
    cmulc_sc(R[3], I[3], T.owr[6], T.owi[6]);
    cmulc_sc(R[4], I[4], T.owr[1], T.owi[1]);
    cmulc_sc(R[5], I[5], T.owr[5], T.owi[5]);
    cmulc_sc(R[6], I[6], T.owr[3], T.owi[3]);
    cmulc_sc(R[7], I[7], T.owr[7], T.owi[7]);
#pragma unroll
    for (int b = 0; b < 8; b += 2) {
        u64 br = R[b + 1], bi = I[b + 1];
        R[b + 1] = f2sub(R[b], br);  I[b + 1] = f2sub(I[b], bi);
        R[b] = f2add(R[b], br);      I[b] = f2add(I[b], bi);
    }
    {
        u64 t;
        t = f2neg(I[3]);  I[3] = R[3];  R[3] = t;
        t = f2neg(I[7]);  I[7] = R[7];  R[7] = t;
        u64 br, bi;
        br = R[2];  bi = I[2];
        R[2] = f2sub(R[0], br);  I[2] = f2sub(I[0], bi);
        R[0] = f2add(R[0], br);  I[0] = f2add(I[0], bi);
        br = R[3];  bi = I[3];
        R[3] = f2sub(R[1], br);  I[3] = f2sub(I[1], bi);
        R[1] = f2add(R[1], br);  I[1] = f2add(I[1], bi);
        br = R[6];  bi = I[6];
        R[6] = f2sub(R[4], br);  I[6] = f2sub(I[4], bi);
        R[4] = f2add(R[4], br);  I[4] = f2add(I[4], bi);
        br = R[7];  bi = I[7];
        R[7] = f2sub(R[5], br);  I[7] = f2sub(I[5], bi);
        R[5] = f2add(R[5], br);  I[5] = f2add(I[5], bi);
    }
    {
        u64 nr, ni, t;
        nr = f2mul(f2sub(R[5], I[5]), T.K);
        ni = f2mul(f2add(R[5], I[5]), T.K);
        R[5] = nr;  I[5] = ni;
        t = f2neg(I[6]);  I[6] = R[6];  R[6] = t;
        nr = f2mul(f2neg(f2add(R[7], I[7])), T.K);
        ni = f2mul(f2sub(R[7], I[7]), T.K);
        R[7] = nr;  I[7] = ni;
#pragma unroll
        for (int j = 0; j < 4; j++) {
            u64 br = R[j + 4], bi = I[j + 4];
            R[j + 4] = f2sub(R[j], br);  I[j + 4] = f2sub(I[j], bi);
            R[j] = f2add(R[j], br);      I[j] = f2add(I[j], bi);
        }
    }
}

__device__ __forceinline__ void applyH(u64 (&R)[8], u64 (&I)[8],
                                       const float (&Hr)[8], const float (&Hi)[8])
{
#pragma unroll
    for (int j = 0; j < 8; j++)
        cmul_sc(R[j], I[j], Hr[j], Hi[j]);
}

__device__ __forceinline__ void transmit(u64 (&R)[8], u64 (&I)[8],
                                         const float2* __restrict__ tA,
                                         const float2* __restrict__ tB, int l16)
{
#pragma unroll
    for (int j = 0; j < 8; j++) {
        const int e = l16 + 16 * j;
        float2 a = tA[e], b = tB[e];
        u64 Tr = pk(a.x, b.x), Ti = pk(a.y, b.y);
        u64 rr = f2sub(f2mul(R[j], Tr), f2mul(I[j], Ti));
        I[j] = f2fma(R[j], Ti, f2mul(I[j], Tr));
        R[j] = rr;
    }
}

// -------------------- precompute T = exp(iV), both orientations -------------
__global__ void msp_maketrans(const float* __restrict__ V)
{
    __shared__ float2 tile[32][33];
    const int z  = blockIdx.z;
    const int by = blockIdx.y * 32, bx = blockIdx.x * 32;
    const int tx = threadIdx.x, ty = threadIdx.y;
#pragma unroll
    for (int dy = ty; dy < 32; dy += 8) {
        const int y = by + dy, x = bx + tx;
        float v = V[(z * 512 + y) * 512 + x];
        float s, c;
        __sincosf(v, &s, &c);
        float2 t = make_float2(c, s);
        g_trow[(z * 512 + y) * 512 + x] = t;
        tile[dy][tx] = t;
    }
    __syncthreads();
#pragma unroll
    for (int dx = ty; dx < 32; dx += 8) {
        const int x = bx + dx, y = by + tx;
        g_tcol[(z * 512 + x) * 512 + y] = tile[tx][dx];
    }
}

// ------------------------------- main kernel --------------------------------
__global__ void __launch_bounds__(512, 1)
msp_main(const float* __restrict__ pre,
         const float* __restrict__ pim,
         const int*   __restrict__ ipos)
{
    extern __shared__ u64 smem[];
    u64* sR2 = smem;                 // pair-packed Re: [pair q][c]
    u64* sI2 = smem + 64 * PITCH2;   // pair-packed Im

    const int bid = blockIdx.x;
    const int k   = bid & 255;
    const int m   = bid >> 8;

    int py, px;
    {
        bool i64 = (ipos[1] | ipos[3] | ipos[5] | ipos[7] |
                    ipos[9] | ipos[11] | ipos[13] | ipos[15]) == 0;
        if (i64) { py = ipos[4 * k];  px = ipos[4 * k + 2]; }
        else     { py = ipos[2 * k];  px = ipos[2 * k + 1]; }
    }

    const int tid = threadIdx.x;
    const int l   = tid & 31;
    const int w   = tid >> 5;        // 16 warps
    const int l16 = l & 15;
    const int h   = l >> 4;
    const int baseLine = 2 * (w & 3) + 8 * h + 16 * ((w >> 2) & 1) + 32 * (w >> 3);

    Tw4 T;
    {
        T.owr[0] = 1.0f;  T.owi[0] = 0.0f;
#pragma unroll
        for (int t = 1; t < 8; t++) {
            float s, c; sincospif((float)(l16 * t) * (1.0f / 64.0f), &s, &c);
            T.owr[t] = c;  T.owi[t] = -s;
        }
        T.K = pk(RSQRT2, RSQRT2);
        { float s, c; sincospif((float)(8 * (l16 & 7)) * (1.0f / 64.0f), &s, &c);
          float tr = (l16 & 8) ? c : 1.0f, ti = (l16 & 8) ? -s : 0.0f;
          T.c8r = pk(tr, tr);  T.c8i = pk(ti, ti); }
        { float s, c; sincospif((float)(16 * (l16 & 3)) * (1.0f / 64.0f), &s, &c);
          float tr = (l16 & 4) ? c : 1.0f, ti = (l16 & 4) ? -s : 0.0f;
          T.c4r = pk(tr, tr);  T.c4i = pk(ti, ti); }
        { float s, c; sincospif((float)(32 * (l16 & 1)) * (1.0f / 64.0f), &s, &c);
          float tr = (l16 & 2) ? c : 1.0f, ti = (l16 & 2) ? -s : 0.0f;
          T.c2r = pk(tr, tr);  T.c2i = pk(ti, ti); }
        float s8 = (l16 & 8) ? -1.0f : 1.0f;  T.sg8 = pk(s8, s8);
        float s4 = (l16 & 4) ? -1.0f : 1.0f;  T.sg4 = pk(s4, s4);
        float s2 = (l16 & 2) ? -1.0f : 1.0f;  T.sg2 = pk(s2, s2);
        float s1 = (l16 & 1) ? -1.0f : 1.0f;  T.sg1 = pk(s1, s1);
    }

    // Fresnel factors at bit-reversed stored positions, 1/128 folded in
    float Hr[8], Hi[8];
#pragma unroll
    for (int j = 0; j < 8; j++) {
        int idx = l16 + 16 * j;
        int fb  = (int)(__brev((unsigned)idx) >> 25);
        float f = (float)(fb < 64 ? fb : fb - 128) * (1.0f / 25.6f);
        float s, c;
        sincospif(-0.25f * f * f, &s, &c);      // lambda*dz = 0.25
        Hr[j] = c * (1.0f / 128.0f);
        Hi[j] = s * (1.0f / 128.0f);
    }

    const float* prm  = pre + m * 16384;
    const float* pimm = pim + m * 16384;

#pragma unroll 1
    for (int pass = 0; pass < 9; pass++) {
        const bool rows = (pass & 1) == 0;
#pragma unroll 1
        for (int p = 0; p < 2; p++) {
            const int lineA = baseLine + 64 * p, lineB = lineA + 1;
            const int q = lineA >> 1;               // pair index (rows passes)
            u64 R[8], I[8];

            // ---- prefetch mid-transmit T lines into L1 (hides under FFT) ----
            const float2* midbase = 0;
            if (pass >= 1 && pass <= 7) {
                midbase = rows
                    ? g_trow + (pass * 512 + py) * 512 + px
                    : g_tcol + (pass * 512 + px) * 512 + py;
#pragma unroll
                for (int j = 0; j < 8; j++) {
                    pref_l1(midbase + lineA * 512 + l16 + 16 * j);
                    pref_l1(midbase + lineB * 512 + l16 + 16 * j);
                }
            }

            // ---- load ----
            if (pass == 0) {
#pragma unroll
                for (int j = 0; j < 8; j++) {
                    const int c = l16 + 16 * j;
                    R[j] = pk(prm[lineA * 128 + c],  prm[lineB * 128 + c]);
                    I[j] = pk(pimm[lineA * 128 + c], pimm[lineB * 128 + c]);
                }
            } else if (rows) {
#pragma unroll
                for (int j = 0; j < 8; j++) {
                    const int c = l16 + 16 * j;
                    R[j] = sR2[q * PITCH2 + c];
                    I[j] = sI2[q * PITCH2 + c];
                }
            } else {
                const int rb = l16 & 1;
#pragma unroll
                for (int j = 0; j < 8; j++) {
                    const int rq = (l16 >> 1) + 8 * j;
                    const float* fr = (const float*)(sR2 + rq * PITCH2 + lineA);
                    const float* fi = (const float*)(sI2 + rq * PITCH2 + lineA);
                    R[j] = pk(fr[rb], fr[rb + 2]);
                    I[j] = pk(fi[rb], fi[rb + 2]);
                }
            }

            // ---- pre-transmit (pass 0 only) ----
            if (pass == 0) {
                const float2* base = g_trow + py * 512 + px;
                transmit(R, I, base + lineA * 512, base + lineB * 512, l16);
            }

            dif8(R, I, T);
            if (pass <= 7) {
                applyH(R, I, Hr, Hi);
                dit8(R, I, T);
            }

            // ---- mid-transmit + second FFT block ----
            if (pass >= 1 && pass <= 7) {
                transmit(R, I, midbase + lineA * 512, midbase + lineB * 512, l16);
                dif8(R, I, T);
                if (pass <= 6) {            // pass 7: detector y-FFT, no H/dit
                    applyH(R, I, Hr, Hi);
                    dit8(R, I, T);
                }
            }

            // ---- store ----
            if (pass == 8) {
#pragma unroll
                for (int j = 0; j < 8; j++) {
                    const int c = l16 + 16 * j;
                    sR2[q * PITCH2 + c] = f2fma(R[j], R[j], f2mul(I[j], I[j]));
                }
            } else if (rows) {
#pragma unroll
                for (int j = 0; j < 8; j++) {
                    const int c = l16 + 16 * j;
                    sR2[q * PITCH2 + c] = R[j];
                    sI2[q * PITCH2 + c] = I[j];
                }
            } else {
                const int rb = l16 & 1;
#pragma unroll
                for (int j = 0; j < 8; j++) {
                    const int rq = (l16 >> 1) + 8 * j;
                    float* fr = (float*)(sR2 + rq * PITCH2 + lineA);
                    float* fi = (float*)(sI2 + rq * PITCH2 + lineA);
                    float a, b;
                    upk(R[j], a, b);  fr[rb] = a;  fr[rb + 2] = b;
                    upk(I[j], a, b);  fi[rb] = a;  fi[rb + 2] = b;
                }
            }
        }
        __syncthreads();
    }

    // bitrev permute |psi|^2 to natural order, vectorized STG.128
    {
        float4* out4 = (float4*)(g_int + ((size_t)bid << 14));
        for (int i = tid; i < 4096; i += 512) {
            const int y = i >> 5;
            const int qx = i & 31;
            const int ry = (int)(__brev((unsigned)y) >> 25);
            const int bx = (int)(__brev((unsigned)qx) >> 27);
            const float* row = (const float*)(sR2 + (ry >> 1) * PITCH2);
            const int cc = ry & 1;
            float4 v;
            v.x = row[2 * bx + cc];
            v.y = row[2 * (bx + 64) + cc];
            v.z = row[2 * (bx + 32) + cc];
            v.w = row[2 * (bx + 96) + cc];
            out4[i] = v;
        }
    }
}

// ------------------------------ finalize ------------------------------------
__global__ void msp_finalize(float* __restrict__ outp)
{
    const size_t i = ((size_t)blockIdx.x * blockDim.x + threadIdx.x) * 4;
    float4 a = *(const float4*)(g_int + i);
    float4 b = *(const float4*)(g_int + i + ((size_t)1 << 22));
    float4 c = *(const float4*)(g_int + i + ((size_t)2 << 22));
    float4 d = *(const float4*)(g_int + i + ((size_t)3 << 22));
    float4 o;
    o.x = sqrtf(1e-10f + (a.x + b.x + c.x + d.x) * (1.0f / 16384.0f));
    o.y = sqrtf(1e-10f + (a.y + b.y + c.y + d.y) * (1.0f / 16384.0f));
    o.z = sqrtf(1e-10f + (a.z + b.z + c.z + d.z) * (1.0f / 16384.0f));
    o.w = sqrtf(1e-10f + (a.w + b.w + c.w + d.w) * (1.0f / 16384.0f));
    *(float4*)(outp + i) = o;
}

// ------------------------------ launcher ------------------------------------
extern "C" void kernel_launch(void* const* d_in, const int* in_sizes, int n_in,
                              void* d_out, int out_size)
{
    const float* V   = (const float*)d_in[0];
    const float* pre = (const float*)d_in[1];
    const float* pim = (const float*)d_in[2];
    const int*   pos = (const int*)d_in[3];
    float* out = (float*)d_out;
    (void)in_sizes; (void)n_in; (void)out_size;

    msp_maketrans<<<dim3(16, 16, 8), dim3(32, 8)>>>(V);

    cudaFuncSetAttribute((const void*)msp_main,
                         cudaFuncAttributeMaxDynamicSharedMemorySize,
                         SMEM_BYTES);
    msp_main<<<1024, 512, SMEM_BYTES>>>(pre, pim, pos);
    msp_finalize<<<4096, 256>>>(out);
}

// round 16
// speedup vs baseline: 1.0452x; 1.0452x over previous
#include <cuda_runtime.h>

// ---------------------------------------------------------------------------
// Multi-slice ptychography, fused, f32x2-packed, 9-pass schedule.
//  0 R: probe, xT0, conv        5 C: conv, xT5, conv
//  1 C: conv, xT1, conv         6 R: conv, xT6, conv
//  2 R: conv, xT2, conv         7 C: conv, xT7, DIF(det-y)
//  3 C: conv, xT3, conv         8 R: DIF(det-x), |.|^2
//  4 R: conv, xT4, conv
// SMEM pair-packed u64[pair][c]; rows passes use direct LDS.64/STS.64.
// T=exp(iV) precomputed both orientations. Span-2 cross twiddle is exactly
// {1, -i} -> implemented as predicated swap/negate on the ALU pipe instead
// of a 4-FP complex multiply (FMA pipe is the binding resource).
// ---------------------------------------------------------------------------

typedef unsigned long long u64;

#define PITCH2 129                       // u64 units per pair-row
#define SMEM_BYTES (2 * 64 * PITCH2 * 8) // 132096
#define RSQRT2 0.70710678118654752440f

static __device__ float  g_int[4u * 256u * 128u * 128u];    // 64 MB scratch
static __device__ float2 g_trow[8u * 512u * 512u];          // 16 MB T row-major
static __device__ float2 g_tcol[8u * 512u * 512u];          // 16 MB T transposed

// ----------------------------- f32x2 helpers --------------------------------
__device__ __forceinline__ u64 pk(float a, float b) {
    u64 r; asm("mov.b64 %0,{%1,%2};" : "=l"(r) : "f"(a), "f"(b)); return r;
}
__device__ __forceinline__ void upk(u64 v, float& a, float& b) {
    asm("mov.b64 {%0,%1},%2;" : "=f"(a), "=f"(b) : "l"(v));
}
__device__ __forceinline__ u64 f2add(u64 a, u64 b) {
    u64 d; asm("add.rn.f32x2 %0,%1,%2;" : "=l"(d) : "l"(a), "l"(b)); return d;
}
__device__ __forceinline__ u64 f2sub(u64 a, u64 b) {
    u64 d; asm("sub.rn.f32x2 %0,%1,%2;" : "=l"(d) : "l"(a), "l"(b)); return d;
}
__device__ __forceinline__ u64 f2mul(u64 a, u64 b) {
    u64 d; asm("mul.rn.f32x2 %0,%1,%2;" : "=l"(d) : "l"(a), "l"(b)); return d;
}
__device__ __forceinline__ u64 f2fma(u64 a, u64 b, u64 c) {
    u64 d; asm("fma.rn.f32x2 %0,%1,%2,%3;" : "=l"(d) : "l"(a), "l"(b), "l"(c)); return d;
}
__device__ __forceinline__ u64 f2neg(u64 v) {
    return v ^ 0x8000000080000000ull;
}
__device__ __forceinline__ u64 shx(u64 v, int s) {
    float a, b; upk(v, a, b);
    a = __shfl_xor_sync(0xffffffffu, a, s);
    b = __shfl_xor_sync(0xffffffffu, b, s);
    return pk(a, b);
}

__device__ __forceinline__ void cmul_sc(u64& r, u64& i, float tr, float ti) {
    u64 Tr = pk(tr, tr), Ti = pk(ti, ti);
    u64 rr = f2sub(f2mul(r, Tr), f2mul(i, Ti));
    i = f2fma(r, Ti, f2mul(i, Tr));
    r = rr;
}
__device__ __forceinline__ void cmulc_sc(u64& r, u64& i, float tr, float ti) {
    u64 Tr = pk(tr, tr), Ti = pk(ti, ti);
    u64 rr = f2fma(i, Ti, f2mul(r, Tr));
    i = f2sub(f2mul(i, Tr), f2mul(r, Ti));
    r = rr;
}

// ------------------------- twiddle context ----------------------------------
struct Tw4 {
    float owr[8], owi[8];     // outer twiddles W^(l16*t)
    u64 K;
    u64 c8r, c8i, c4r, c4i;   // effective cross twiddles, spans 8 and 4
    u64 sg8, sg4, sg2, sg1;   // butterfly signs
    bool p3;                  // (l16 & 3) == 3  -> span-2 twiddle = -i
};

__device__ __forceinline__ void cross_dif(u64 (&R)[8], u64 (&I)[8], int s,
                                          u64 sg, u64 cr, u64 ci)
{
    u64 nci = f2neg(ci);
#pragma unroll
    for (int j = 0; j < 8; j++) {
        u64 pR = shx(R[j], s), pI = shx(I[j], s);
        u64 xR = f2fma(sg, R[j], pR);
        u64 xI = f2fma(sg, I[j], pI);
        R[j] = f2fma(xI, nci, f2mul(xR, cr));
        I[j] = f2fma(xI, cr,  f2mul(xR, ci));
    }
}
__device__ __forceinline__ void cross_dit(u64 (&R)[8], u64 (&I)[8], int s,
                                          u64 sg, u64 cr, u64 ci)
{
    u64 nci = f2neg(ci);
#pragma unroll
    for (int j = 0; j < 8; j++) {
        u64 uR = f2fma(I[j], ci,  f2mul(R[j], cr));
        u64 uI = f2fma(R[j], nci, f2mul(I[j], cr));
        u64 pR = shx(uR, s), pI = shx(uI, s);
        R[j] = f2fma(sg, uR, pR);
        I[j] = f2fma(sg, uI, pI);
    }
}
// span-2 DIF: twiddle = -i on p3 lanes (swap+neg, ALU pipe), identity else
__device__ __forceinline__ void cross_dif2(u64 (&R)[8], u64 (&I)[8],
                                           u64 sg, bool p3)
{
#pragma unroll
    for (int j = 0; j < 8; j++) {
        u64 pR = shx(R[j], 2), pI = shx(I[j], 2);
        u64 xR = f2fma(sg, R[j], pR);
        u64 xI = f2fma(sg, I[j], pI);
        R[j] = p3 ? xI : xR;
        I[j] = p3 ? f2neg(xR) : xI;
    }
}
// span-2 DIT: conj twiddle = +i on p3 lanes, applied before the shuffle
__device__ __forceinline__ void cross_dit2(u64 (&R)[8], u64 (&I)[8],
                                           u64 sg, bool p3)
{
#pragma unroll
    for (int j = 0; j < 8; j++) {
        u64 uR = p3 ? f2neg(I[j]) : R[j];
        u64 uI = p3 ? R[j] : I[j];
        u64 pR = shx(uR, 2), pI = shx(uI, 2);
        R[j] = f2fma(sg, uR, pR);
        I[j] = f2fma(sg, uI, pI);
    }
}

__device__ __forceinline__ void dif8(u64 (&R)[8], u64 (&I)[8], const Tw4& T)
{
    {
        u64 dr, di;
        dr = f2sub(R[0], R[4]);  di = f2sub(I[0], I[4]);
        R[0] = f2add(R[0], R[4]);  I[0] = f2add(I[0], I[4]);
        R[4] = dr;  I[4] = di;
        dr = f2sub(R[1], R[5]);  di = f2sub(I[1], I[5]);
        R[1] = f2add(R[1], R[5]);  I[1] = f2add(I[1], I[5]);
        R[5] = f2mul(f2add(dr, di), T.K);
        I[5] = f2mul(f2sub(di, dr), T.K);
        dr = f2sub(R[2], R[6]);  di = f2sub(I[2], I[6]);
        R[2] = f2add(R[2], R[6]);  I[2] = f2add(I[2], I[6]);
        R[6] = di;  I[6] = f2neg(dr);
        dr = f2sub(R[3], R[7]);  di = f2sub(I[3], I[7]);
        R[3] = f2add(R[3], R[7]);  I[3] = f2add(I[3], I[7]);
        R[7] = f2mul(f2sub(di, dr), T.K);
        I[7] = f2mul(f2neg(f2add(dr, di)), T.K);
    }
    {
        u64 dr, di;
        dr = f2sub(R[0], R[2]);  di = f2sub(I[0], I[2]);
        R[0] = f2add(R[0], R[2]);  I[0] = f2add(I[0], I[2]);
        R[2] = dr;  I[2] = di;
        dr = f2sub(R[4], R[6]);  di = f2sub(I[4], I[6]);
        R[4] = f2add(R[4], R[6]);  I[4] = f2add(I[4], I[6]);
        R[6] = dr;  I[6] = di;
        dr = f2sub(R[1], R[3]);  di = f2sub(I[1], I[3]);
        R[1] = f2add(R[1], R[3]);  I[1] = f2add(I[1], I[3]);
        R[3] = di;  I[3] = f2neg(dr);
        dr = f2sub(R[5], R[7]);  di = f2sub(I[5], I[7]);
        R[5] = f2add(R[5], R[7]);  I[5] = f2add(I[5], I[7]);
        R[7] = di;  I[7] = f2neg(dr);
    }
#pragma unroll
    for (int b = 0; b < 8; b += 2) {
        u64 dr = f2sub(R[b], R[b + 1]), di = f2sub(I[b], I[b + 1]);
        R[b] = f2add(R[b], R[b + 1]);  I[b] = f2add(I[b], I[b + 1]);
        R[b + 1] = dr;  I[b + 1] = di;
    }
    cmul_sc(R[1], I[1], T.owr[4], T.owi[4]);
    cmul_sc(R[2], I[2], T.owr[2], T.owi[2]);
    cmul_sc(R[3], I[3], T.owr[6], T.owi[6]);
    cmul_sc(R[4], I[4], T.owr[1], T.owi[1]);
    cmul_sc(R[5], I[5], T.owr[5], T.owi[5]);
    cmul_sc(R[6], I[6], T.owr[3], T.owi[3]);
    cmul_sc(R[7], I[7], T.owr[7], T.owi[7]);
    cross_dif(R, I, 8, T.sg8, T.c8r, T.c8i);
    cross_dif(R, I, 4, T.sg4, T.c4r, T.c4i);
    cross_dif2(R, I, T.sg2, T.p3);
#pragma unroll
    for (int j = 0; j < 8; j++) {
        u64 pR = shx(R[j], 1), pI = shx(I[j], 1);
        R[j] = f2fma(T.sg1, R[j], pR);
        I[j] = f2fma(T.sg1, I[j], pI);
    }
}

__device__ __forceinline__ void dit8(u64 (&R)[8], u64 (&I)[8], const Tw4& T)
{
#pragma unroll
    for (int j = 0; j < 8; j++) {
        u64 pR = shx(R[j], 1), pI = shx(I[j], 1);
        R[j] = f2fma(T.sg1, R[j], pR);
        I[j] = f2fma(T.sg1, I[j], pI);
    }
    cross_dit2(R, I, T.sg2, T.p3);
    cross_dit(R, I, 4, T.sg4, T.c4r, T.c4i);
    cross_dit(R, I, 8, T.sg8, T.c8r, T.c8i);
    cmulc_sc(R[1], I[1], T.owr[4], T.owi[4]);
    cmulc_sc(R[2], I[2], T.owr[2], T.owi[2]);
    cmulc_sc(R[3], I[3], T.owr[6], T.owi[6]);
    cmulc_sc(R[4], I[4], T.owr[1], T.owi[1]);
    cmulc_sc(R[5], I[5], T.owr[5], T.owi[5]);
    cmulc_sc(R[6], I[6], T.owr[3], T.owi[3]);
    cmulc_sc(R[7], I[7], T.owr[7], T.owi[7]);
#pragma unroll
    for (int b = 0; b < 8; b += 2) {
        u64 br = R[b + 1], bi = I[b + 1];
        R[b + 1] = f2sub(R[b], br);  I[b + 1] = f2sub(I[b], bi);
        R[b] = f2add(R[b], br);      I[b] = f2add(I[b], bi);
    }
    {
        u64 t;
        t = f2neg(I[3]);  I[3] = R[3];  R[3] = t;
        t = f2neg(I[7]);  I[7] = R[7];  R[7] = t;
        u64 br, bi;
        br = R[2];  bi = I[2];
        R[2] = f2sub(R[0], br);  I[2] = f2sub(I[0], bi);
        R[0] = f2add(R[0], br);  I[0] = f2add(I[0], bi);
        br = R[3];  bi = I[3];
        R[3] = f2sub(R[1], br);  I[3] = f2sub(I[1], bi);
        R[1] = f2add(R[1], br);  I[1] = f2add(I[1], bi);
        br = R[6];  bi = I[6];
        R[6] = f2sub(R[4], br);  I[6] = f2sub(I[4], bi);
        R[4] = f2add(R[4], br);  I[4] = f2add(I[4], bi);
        br = R[7];  bi = I[7];
        R[7] = f2sub(R[5], br);  I[7] = f2sub(I[5], bi);
        R[5] = f2add(R[5], br);  I[5] = f2add(I[5], bi);
    }
    {
        u64 nr, ni, t;
        nr = f2mul(f2sub(R[5], I[5]), T.K);
        ni = f2mul(f2add(R[5], I[5]), T.K);
        R[5] = nr;  I[5] = ni;
        t = f2neg(I[6]);  I[6] = R[6];  R[6] = t;
        nr = f2mul(f2neg(f2add(R[7], I[7])), T.K);
        ni = f2mul(f2sub(R[7], I[7]), T.K);
        R[7] = nr;  I[7] = ni;
#pragma unroll
        for (int j = 0; j < 4; j++) {
            u64 br = R[j + 4], bi = I[j + 4];
            R[j + 4] = f2sub(R[j], br);  I[j + 4] = f2sub(I[j], bi);
            R[j] = f2add(R[j], br);      I[j] = f2add(I[j], bi);
        }
    }
}

__device__ __forceinline__ void applyH(u64 (&R)[8], u64 (&I)[8],
                                       const float (&Hr)[8], const float (&Hi)[8])
{
#pragma unroll
    for (int j = 0; j < 8; j++)
        cmul_sc(R[j], I[j], Hr[j], Hi[j]);
}

__device__ __forceinline__ void transmit(u64 (&R)[8], u64 (&I)[8],
                                         const float2* __restrict__ tA,
                                         const float2* __restrict__ tB, int l16)
{
#pragma unroll
    for (int j = 0; j < 8; j++) {
        const int e = l16 + 16 * j;
        float2 a = tA[e], b = tB[e];
        u64 Tr = pk(a.x, b.x), Ti = pk(a.y, b.y);
        u64 rr = f2sub(f2mul(R[j], Tr), f2mul(I[j], Ti));
        I[j] = f2fma(R[j], Ti, f2mul(I[j], Tr));
        R[j] = rr;
    }
}

// -------------------- precompute T = exp(iV), both orientations -------------
__global__ void msp_maketrans(const float* __restrict__ V)
{
    __shared__ float2 tile[32][33];
    const int z  = blockIdx.z;
    const int by = blockIdx.y * 32, bx = blockIdx.x * 32;
    const int tx = threadIdx.x, ty = threadIdx.y;
#pragma unroll
    for (int dy = ty; dy < 32; dy += 8) {
        const int y = by + dy, x = bx + tx;
        float v = V[(z * 512 + y) * 512 + x];
        float s, c;
        __sincosf(v, &s, &c);
        float2 t = make_float2(c, s);
        g_trow[(z * 512 + y) * 512 + x] = t;
        tile[dy][tx] = t;
    }
    __syncthreads();
#pragma unroll
    for (int dx = ty; dx < 32; dx += 8) {
        const int x = bx + dx, y = by + tx;
        g_tcol[(z * 512 + x) * 512 + y] = tile[tx][dx];
    }
}

// ------------------------------- main kernel --------------------------------
__global__ void __launch_bounds__(512, 1)
msp_main(const float* __restrict__ pre,
         const float* __restrict__ pim,
         const int*   __restrict__ ipos)
{
    extern __shared__ u64 smem[];
    u64* sR2 = smem;                 // pair-packed Re: [pair q][c]
    u64* sI2 = smem + 64 * PITCH2;   // pair-packed Im

    const int bid = blockIdx.x;
    const int k   = bid & 255;
    const int m   = bid >> 8;

    int py, px;
    {
        bool i64 = (ipos[1] | ipos[3] | ipos[5] | ipos[7] |
                    ipos[9] | ipos[11] | ipos[13] | ipos[15]) == 0;
        if (i64) { py = ipos[4 * k];  px = ipos[4 * k + 2]; }
        else     { py = ipos[2 * k];  px = ipos[2 * k + 1]; }
    }

    const int tid = threadIdx.x;
    const int l   = tid & 31;
    const int w   = tid >> 5;        // 16 warps
    const int l16 = l & 15;
    const int h   = l >> 4;
    const int baseLine = 2 * (w & 3) + 8 * h + 16 * ((w >> 2) & 1) + 32 * (w >> 3);

    Tw4 T;
    {
        T.owr[0] = 1.0f;  T.owi[0] = 0.0f;
#pragma unroll
        for (int t = 1; t < 8; t++) {
            float s, c; sincospif((float)(l16 * t) * (1.0f / 64.0f), &s, &c);
            T.owr[t] = c;  T.owi[t] = -s;
        }
        T.K = pk(RSQRT2, RSQRT2);
        { float s, c; sincospif((float)(8 * (l16 & 7)) * (1.0f / 64.0f), &s, &c);
          float tr = (l16 & 8) ? c : 1.0f, ti = (l16 & 8) ? -s : 0.0f;
          T.c8r = pk(tr, tr);  T.c8i = pk(ti, ti); }
        { float s, c; sincospif((float)(16 * (l16 & 3)) * (1.0f / 64.0f), &s, &c);
          float tr = (l16 & 4) ? c : 1.0f, ti = (l16 & 4) ? -s : 0.0f;
          T.c4r = pk(tr, tr);  T.c4i = pk(ti, ti); }
        T.p3 = ((l16 & 3) == 3);
        float s8 = (l16 & 8) ? -1.0f : 1.0f;  T.sg8 = pk(s8, s8);
        float s4 = (l16 & 4) ? -1.0f : 1.0f;  T.sg4 = pk(s4, s4);
        float s2 = (l16 & 2) ? -1.0f : 1.0f;  T.sg2 = pk(s2, s2);
        float s1 = (l16 & 1) ? -1.0f : 1.0f;  T.sg1 = pk(s1, s1);
    }

    // Fresnel factors at bit-reversed stored positions, 1/128 folded in
    float Hr[8], Hi[8];
#pragma unroll
    for (int j = 0; j < 8; j++) {
        int idx = l16 + 16 * j;
        int fb  = (int)(__brev((unsigned)idx) >> 25);
        float f = (float)(fb < 64 ? fb : fb - 128) * (1.0f / 25.6f);
        float s, c;
        sincospif(-0.25f * f * f, &s, &c);      // lambda*dz = 0.25
        Hr[j] = c * (1.0f / 128.0f);
        Hi[j] = s * (1.0f / 128.0f);
    }

    const float* prm  = pre + m * 16384;
    const float* pimm = pim + m * 16384;

#pragma unroll 1
    for (int pass = 0; pass < 9; pass++) {
        const bool rows = (pass & 1) == 0;
#pragma unroll 1
        for (int p = 0; p < 2; p++) {
            const int lineA = baseLine + 64 * p, lineB = lineA + 1;
            const int q = lineA >> 1;               // pair index (rows passes)
            u64 R[8], I[8];

            // ---- load ----
            if (pass == 0) {
#pragma unroll
                for (int j = 0; j < 8; j++) {
                    const int c = l16 + 16 * j;
                    R[j] = pk(prm[lineA * 128 + c],  prm[lineB * 128 + c]);
                    I[j] = pk(pimm[lineA * 128 + c], pimm[lineB * 128 + c]);
                }
            } else if (rows) {
#pragma unroll
                for (int j = 0; j < 8; j++) {
                    const int c = l16 + 16 * j;
                    R[j] = sR2[q * PITCH2 + c];
                    I[j] = sI2[q * PITCH2 + c];
                }
            } else {
                const int rb = l16 & 1;
#pragma unroll
                for (int j = 0; j < 8; j++) {
                    const int rq = (l16 >> 1) + 8 * j;
                    const float* fr = (const float*)(sR2 + rq * PITCH2 + lineA);
                    const float* fi = (const float*)(sI2 + rq * PITCH2 + lineA);
                    R[j] = pk(fr[rb], fr[rb + 2]);
                    I[j] = pk(fi[rb], fi[rb + 2]);
                }
            }

            // ---- pre-transmit (pass 0 only) ----
            if (pass == 0) {
                const float2* base = g_trow + py * 512 + px;
                transmit(R, I, base + lineA * 512, base + lineB * 512, l16);
            }

            dif8(R, I, T);
            if (pass <= 7) {
                applyH(R, I, Hr, Hi);
                dit8(R, I, T);
            }

            // ---- mid-transmit + second FFT block ----
            if (pass >= 1 && pass <= 7) {
                const float2* base = rows
                    ? g_trow + (pass * 512 + py) * 512 + px
                    : g_tcol + (pass * 512 + px) * 512 + py;
                transmit(R, I, base + lineA * 512, base + lineB * 512, l16);
                dif8(R, I, T);
                if (pass <= 6) {            // pass 7: detector y-FFT, no H/dit
                    applyH(R, I, Hr, Hi);
                    dit8(R, I, T);
                }
            }

            // ---- store ----
            if (pass == 8) {
#pragma unroll
                for (int j = 0; j < 8; j++) {
                    const int c = l16 + 16 * j;
                    sR2[q * PITCH2 + c] = f2fma(R[j], R[j], f2mul(I[j], I[j]));
                }
            } else if (rows) {
#pragma unroll
                for (int j = 0; j < 8; j++) {
                    const int c = l16 + 16 * j;
                    sR2[q * PITCH2 + c] = R[j];
                    sI2[q * PITCH2 + c] = I[j];
                }
            } else {
                const int rb = l16 & 1;
#pragma unroll
                for (int j = 0; j < 8; j++) {
                    const int rq = (l16 >> 1) + 8 * j;
                    float* fr = (float*)(sR2 + rq * PITCH2 + lineA);
                    float* fi = (float*)(sI2 + rq * PITCH2 + lineA);
                    float a, b;
                    upk(R[j], a, b);  fr[rb] = a;  fr[rb + 2] = b;
                    upk(I[j], a, b);  fi[rb] = a;  fi[rb + 2] = b;
                }
            }
        }
        __syncthreads();
    }

    // bitrev permute |psi|^2 to natural order, vectorized STG.128
    {
        float4* out4 = (float4*)(g_int + ((size_t)bid << 14));
        for (int i = tid; i < 4096; i += 512) {
            const int y = i >> 5;
            const int qx = i & 31;
            const int ry = (int)(__brev((unsigned)y) >> 25);
            const int bx = (int)(__brev((unsigned)qx) >> 27);
            const float* row = (const float*)(sR2 + (ry >> 1) * PITCH2);
            const int cc = ry & 1;
            float4 v;
            v.x = row[2 * bx + cc];
            v.y = row[2 * (bx + 64) + cc];
            v.z = row[2 * (bx + 32) + cc];
            v.w = row[2 * (bx + 96) + cc];
            out4[i] = v;
        }
    }
}

// ------------------------------ finalize ------------------------------------
__global__ void msp_finalize(float* __restrict__ outp)
{
    const size_t i = ((size_t)blockIdx.x * blockDim.x + threadIdx.x) * 4;
    float4 a = *(const float4*)(g_int + i);
    float4 b = *(const float4*)(g_int + i + ((size_t)1 << 22));
    float4 c = *(const float4*)(g_int + i + ((size_t)2 << 22));
    float4 d = *(const float4*)(g_int + i + ((size_t)3 << 22));
    float4 o;
    o.x = sqrtf(1e-10f + (a.x + b.x + c.x + d.x) * (1.0f / 16384.0f));
    o.y = sqrtf(1e-10f + (a.y + b.y + c.y + d.y) * (1.0f / 16384.0f));
    o.z = sqrtf(1e-10f + (a.z + b.z + c.z + d.z) * (1.0f / 16384.0f));
    o.w = sqrtf(1e-10f + (a.w + b.w + c.w + d.w) * (1.0f / 16384.0f));
    *(float4*)(outp + i) = o;
}

// ------------------------------ launcher ------------------------------------
extern "C" void kernel_launch(void* const* d_in, const int* in_sizes, int n_in,
                              void* d_out, int out_size)
{
    const float* V   = (const float*)d_in[0];
    const float* pre = (const float*)d_in[1];
    const float* pim = (const float*)d_in[2];
    const int*   pos = (const int*)d_in[3];
    float* out = (float*)d_out;
    (void)in_sizes; (void)n_in; (void)out_size;

    msp_maketrans<<<dim3(16, 16, 8), dim3(32, 8)>>>(V);

    cudaFuncSetAttribute((const void*)msp_main,
                         cudaFuncAttributeMaxDynamicSharedMemorySize,
                         SMEM_BYTES);
    msp_main<<<1024, 512, SMEM_BYTES>>>(pre, pim, pos);
    msp_finalize<<<4096, 256>>>(out);
}

// round 17
// speedup vs baseline: 1.0637x; 1.0177x over previous
#include <cuda_runtime.h>

// ---------------------------------------------------------------------------
// Multi-slice ptychography, fused, f32x2-packed, 9-pass schedule.
//  0 R: probe, xT0, conv        5 C: conv, xT5, conv
//  1 C: conv, xT1, conv         6 R: conv, xT6, conv
//  2 R: conv, xT2, conv         7 C: conv, xT7, DIF(det-y)
//  3 C: conv, xT3, conv         8 R: DIF(det-x), |.|^2
//  4 R: conv, xT4, conv
// SMEM pair-packed u64[pair][c]. T=exp(iV) precomputed both orientations.
// Span-2 cross twiddle = {1,-i} via ALU swap/neg. NEW: span1(DIF)∘H∘span1(DIT)
// fused into z = A*x + B*x_partner (A=Hs+Hp, B=sg1*(Hs-Hp)): 2 shfl instead
// of 4 per slot at every H site, and one shuffle-latency round removed.
// ---------------------------------------------------------------------------

typedef unsigned long long u64;

#define PITCH2 129                       // u64 units per pair-row
#define SMEM_BYTES (2 * 64 * PITCH2 * 8) // 132096
#define RSQRT2 0.70710678118654752440f

static __device__ float  g_int[4u * 256u * 128u * 128u];    // 64 MB scratch
static __device__ float2 g_trow[8u * 512u * 512u];          // 16 MB T row-major
static __device__ float2 g_tcol[8u * 512u * 512u];          // 16 MB T transposed

// ----------------------------- f32x2 helpers --------------------------------
__device__ __forceinline__ u64 pk(float a, float b) {
    u64 r; asm("mov.b64 %0,{%1,%2};" : "=l"(r) : "f"(a), "f"(b)); return r;
}
__device__ __forceinline__ void upk(u64 v, float& a, float& b) {
    asm("mov.b64 {%0,%1},%2;" : "=f"(a), "=f"(b) : "l"(v));
}
__device__ __forceinline__ u64 f2add(u64 a, u64 b) {
    u64 d; asm("add.rn.f32x2 %0,%1,%2;" : "=l"(d) : "l"(a), "l"(b)); return d;
}
__device__ __forceinline__ u64 f2sub(u64 a, u64 b) {
    u64 d; asm("sub.rn.f32x2 %0,%1,%2;" : "=l"(d) : "l"(a), "l"(b)); return d;
}
__device__ __forceinline__ u64 f2mul(u64 a, u64 b) {
    u64 d; asm("mul.rn.f32x2 %0,%1,%2;" : "=l"(d) : "l"(a), "l"(b)); return d;
}
__device__ __forceinline__ u64 f2fma(u64 a, u64 b, u64 c) {
    u64 d; asm("fma.rn.f32x2 %0,%1,%2,%3;" : "=l"(d) : "l"(a), "l"(b), "l"(c)); return d;
}
__device__ __forceinline__ u64 f2neg(u64 v) {
    return v ^ 0x8000000080000000ull;
}
__device__ __forceinline__ u64 shx(u64 v, int s) {
    float a, b; upk(v, a, b);
    a = __shfl_xor_sync(0xffffffffu, a, s);
    b = __shfl_xor_sync(0xffffffffu, b, s);
    return pk(a, b);
}

__device__ __forceinline__ void cmul_sc(u64& r, u64& i, float tr, float ti) {
    u64 Tr = pk(tr, tr), Ti = pk(ti, ti);
    u64 rr = f2sub(f2mul(r, Tr), f2mul(i, Ti));
    i = f2fma(r, Ti, f2mul(i, Tr));
    r = rr;
}
__device__ __forceinline__ void cmulc_sc(u64& r, u64& i, float tr, float ti) {
    u64 Tr = pk(tr, tr), Ti = pk(ti, ti);
    u64 rr = f2fma(i, Ti, f2mul(r, Tr));
    i = f2sub(f2mul(i, Tr), f2mul(r, Ti));
    r = rr;
}

// ------------------------- twiddle context ----------------------------------
struct Tw4 {
    float owr[8], owi[8];     // outer twiddles W^(l16*t)
    u64 K;
    u64 c8r, c8i, c4r, c4i;   // effective cross twiddles, spans 8 and 4
    u64 sg8, sg4, sg2, sg1;   // butterfly signs
    bool p3;                  // (l16 & 3) == 3  -> span-2 twiddle = -i
};

__device__ __forceinline__ void cross_dif(u64 (&R)[8], u64 (&I)[8], int s,
                                          u64 sg, u64 cr, u64 ci)
{
    u64 nci = f2neg(ci);
#pragma unroll
    for (int j = 0; j < 8; j++) {
        u64 pR = shx(R[j], s), pI = shx(I[j], s);
        u64 xR = f2fma(sg, R[j], pR);
        u64 xI = f2fma(sg, I[j], pI);
        R[j] = f2fma(xI, nci, f2mul(xR, cr));
        I[j] = f2fma(xI, cr,  f2mul(xR, ci));
    }
}
__device__ __forceinline__ void cross_dit(u64 (&R)[8], u64 (&I)[8], int s,
                                          u64 sg, u64 cr, u64 ci)
{
    u64 nci = f2neg(ci);
#pragma unroll
    for (int j = 0; j < 8; j++) {
        u64 uR = f2fma(I[j], ci,  f2mul(R[j], cr));
        u64 uI = f2fma(R[j], nci, f2mul(I[j], cr));
        u64 pR = shx(uR, s), pI = shx(uI, s);
        R[j] = f2fma(sg, uR, pR);
        I[j] = f2fma(sg, uI, pI);
    }
}
// span-2 DIF: twiddle = -i on p3 lanes (swap+neg, ALU pipe), identity else
__device__ __forceinline__ void cross_dif2(u64 (&R)[8], u64 (&I)[8],
                                           u64 sg, bool p3)
{
#pragma unroll
    for (int j = 0; j < 8; j++) {
        u64 pR = shx(R[j], 2), pI = shx(I[j], 2);
        u64 xR = f2fma(sg, R[j], pR);
        u64 xI = f2fma(sg, I[j], pI);
        R[j] = p3 ? xI : xR;
        I[j] = p3 ? f2neg(xR) : xI;
    }
}
// span-2 DIT: conj twiddle = +i on p3 lanes, applied before the shuffle
__device__ __forceinline__ void cross_dit2(u64 (&R)[8], u64 (&I)[8],
                                           u64 sg, bool p3)
{
#pragma unroll
    for (int j = 0; j < 8; j++) {
        u64 uR = p3 ? f2neg(I[j]) : R[j];
        u64 uI = p3 ? R[j] : I[j];
        u64 pR = shx(uR, 2), pI = shx(uI, 2);
        R[j] = f2fma(sg, uR, pR);
        I[j] = f2fma(sg, uI, pI);
    }
}
// plain span-1 butterfly (used when DIF stands alone)
__device__ __forceinline__ void span1(u64 (&R)[8], u64 (&I)[8], u64 sg1)
{
#pragma unroll
    for (int j = 0; j < 8; j++) {
        u64 pR = shx(R[j], 1), pI = shx(I[j], 1);
        R[j] = f2fma(sg1, R[j], pR);
        I[j] = f2fma(sg1, I[j], pI);
    }
}
// fused span1(DIF) * H * span1(DIT):  z = A*x + B*x_partner
__device__ __forceinline__ void fusedH(u64 (&R)[8], u64 (&I)[8],
                                       const float (&Ar)[8], const float (&Ai)[8],
                                       const float (&Br)[8], const float (&Bi)[8])
{
#pragma unroll
    for (int j = 0; j < 8; j++) {
        u64 pR = shx(R[j], 1), pI = shx(I[j], 1);
        u64 ArP = pk(Ar[j], Ar[j]), AiP = pk(Ai[j], Ai[j]);
        u64 BrP = pk(Br[j], Br[j]), BiP = pk(Bi[j], Bi[j]);
        u64 u = f2fma(pR, BrP, f2mul(R[j], ArP));
        u64 v = f2fma(pI, BiP, f2mul(I[j], AiP));
        u64 w = f2fma(R[j], AiP, f2mul(I[j], ArP));
        w = f2fma(pI, BrP, w);
        I[j] = f2fma(pR, BiP, w);
        R[j] = f2sub(u, v);
    }
}

// dif8 WITHOUT the final span-1 stage
__device__ __forceinline__ void dif8_head(u64 (&R)[8], u64 (&I)[8], const Tw4& T)
{
    {
        u64 dr, di;
        dr = f2sub(R[0], R[4]);  di = f2sub(I[0], I[4]);
        R[0] = f2add(R[0], R[4]);  I[0] = f2add(I[0], I[4]);
        R[4] = dr;  I[4] = di;
        dr = f2sub(R[1], R[5]);  di = f2sub(I[1], I[5]);
        R[1] = f2add(R[1], R[5]);  I[1] = f2add(I[1], I[5]);
        R[5] = f2mul(f2add(dr, di), T.K);
        I[5] = f2mul(f2sub(di, dr), T.K);
        dr = f2sub(R[2], R[6]);  di = f2sub(I[2], I[6]);
        R[2] = f2add(R[2], R[6]);  I[2] = f2add(I[2], I[6]);
        R[6] = di;  I[6] = f2neg(dr);
        dr = f2sub(R[3], R[7]);  di = f2sub(I[3], I[7]);
        R[3] = f2add(R[3], R[7]);  I[3] = f2add(I[3], I[7]);
        R[7] = f2mul(f2sub(di, dr), T.K);
        I[7] = f2mul(f2neg(f2add(dr, di)), T.K);
    }
    {
        u64 dr, di;
        dr = f2sub(R[0], R[2]);  di = f2sub(I[0], I[2]);
        R[0] = f2add(R[0], R[2]);  I[0] = f2add(I[0], I[2]);
        R[2] = dr;  I[2] = di;
        dr = f2sub(R[4], R[6]);  di = f2sub(I[4], I[6]);
        R[4] = f2add(R[4], R[6]);  I[4] = f2add(I[4], I[6]);
        R[6] = dr;  I[6] = di;
        dr = f2sub(R[1], R[3]);  di = f2sub(I[1], I[3]);
        R[1] = f2add(R[1], R[3]);  I[1] = f2add(I[1], I[3]);
        R[3] = di;  I[3] = f2neg(dr);
        dr = f2sub(R[5], R[7]);  di = f2sub(I[5], I[7]);
        R[5] = f2add(R[5], R[7]);  I[5] = f2add(I[5], I[7]);
        R[7] = di;  I[7] = f2neg(dr);
    }
#pragma unroll
    for (int b = 0; b < 8; b += 2) {
        u64 dr = f2sub(R[b], R[b + 1]), di = f2sub(I[b], I[b + 1]);
        R[b] = f2add(R[b], R[b + 1]);  I[b] = f2add(I[b], I[b + 1]);
        R[b + 1] = dr;  I[b + 1] = di;
    }
    cmul_sc(R[1], I[1], T.owr[4], T.owi[4]);
    cmul_sc(R[2], I[2], T.owr[2], T.owi[2]);
    cmul_sc(R[3], I[3], T.owr[6], T.owi[6]);
    cmul_sc(R[4], I[4], T.owr[1], T.owi[1]);
    cmul_sc(R[5], I[5], T.owr[5], T.owi[5]);
    cmul_sc(R[6], I[6], T.owr[3], T.owi[3]);
    cmul_sc(R[7], I[7], T.owr[7], T.owi[7]);
    cross_dif(R, I, 8, T.sg8, T.c8r, T.c8i);
    cross_dif(R, I, 4, T.sg4, T.c4r, T.c4i);
    cross_dif2(R, I, T.sg2, T.p3);
}

// dit8 WITHOUT the initial span-1 stage
__device__ __forceinline__ void dit8_tail(u64 (&R)[8], u64 (&I)[8], const Tw4& T)
{
    cross_dit2(R, I, T.sg2, T.p3);
    cross_dit(R, I, 4, T.sg4, T.c4r, T.c4i);
    cross_dit(R, I, 8, T.sg8, T.c8r, T.c8i);
    cmulc_sc(R[1], I[1], T.owr[4], T.owi[4]);
    cmulc_sc(R[2], I[2], T.owr[2], T.owi[2]);
    cmulc_sc(R[3], I[3], T.owr[6], T.owi[6]);
    cmulc_sc(R[4], I[4], T.owr[1], T.owi[1]);
    cmulc_sc(R[5], I[5], T.owr[5], T.owi[5]);
    cmulc_sc(R[6], I[6], T.owr[3], T.owi[3]);
    cmulc_sc(R[7], I[7], T.owr[7], T.owi[7]);
#pragma unroll
    for (int b = 0; b < 8; b += 2) {
        u64 br = R[b + 1], bi = I[b + 1];
        R[b + 1] = f2sub(R[b], br);  I[b + 1] = f2sub(I[b], bi);
        R[b] = f2add(R[b], br);      I[b] = f2add(I[b], bi);
    }
    {
        u64 t;
        t = f2neg(I[3]);  I[3] = R[3];  R[3] = t;
        t = f2neg(I[7]);  I[7] = R[7];  R[7] = t;
        u64 br, bi;
        br = R[2];  bi = I[2];
        R[2] = f2sub(R[0], br);  I[2] = f2sub(I[0], bi);
        R[0] = f2add(R[0], br);  I[0] = f2add(I[0], bi);
        br = R[3];  bi = I[3];
        R[3] = f2sub(R[1], br);  I[3] = f2sub(I[1], bi);
        R[1] = f2add(R[1], br);  I[1] = f2add(I[1], bi);
        br = R[6];  bi = I[6];
        R[6] = f2sub(R[4], br);  I[6] = f2sub(I[4], bi);
        R[4] = f2add(R[4], br);  I[4] = f2add(I[4], bi);
        br = R[7];  bi = I[7];
        R[7] = f2sub(R[5], br);  I[7] = f2sub(I[5], bi);
        R[5] = f2add(R[5], br);  I[5] = f2add(I[5], bi);
    }
    {
        u64 nr, ni, t;
        nr = f2mul(f2sub(R[5], I[5]), T.K);
        ni = f2mul(f2add(R[5], I[5]), T.K);
        R[5] = nr;  I[5] = ni;
        t = f2neg(I[6]);  I[6] = R[6];  R[6] = t;
        nr = f2mul(f2neg(f2add(R[7], I[7])), T.K);
        ni = f2mul(f2sub(R[7], I[7]), T.K);
        R[7] = nr;  I[7] = ni;
#pragma unroll
        for (int j = 0; j < 4; j++) {
            u64 br = R[j + 4], bi = I[j + 4];
            R[j + 4] = f2sub(R[j], br);  I[j + 4] = f2sub(I[j], bi);
            R[j] = f2add(R[j], br);      I[j] = f2add(I[j], bi);
        }
    }
}

__device__ __forceinline__ void transmit(u64 (&R)[8], u64 (&I)[8],
                                         const float2* __restrict__ tA,
                                         const float2* __restrict__ tB, int l16)
{
#pragma unroll
    for (int j = 0; j < 8; j++) {
        const int e = l16 + 16 * j;
        float2 a = tA[e], b = tB[e];
        u64 Tr = pk(a.x, b.x), Ti = pk(a.y, b.y);
        u64 rr = f2sub(f2mul(R[j], Tr), f2mul(I[j], Ti));
        I[j] = f2fma(R[j], Ti, f2mul(I[j], Tr));
        R[j] = rr;
    }
}

// -------------------- precompute T = exp(iV), both orientations -------------
__global__ void msp_maketrans(const float* __restrict__ V)
{
    __shared__ float2 tile[32][33];
    const int z  = blockIdx.z;
    const int by = blockIdx.y * 32, bx = blockIdx.x * 32;
    const int tx = threadIdx.x, ty = threadIdx.y;
#pragma unroll
    for (int dy = ty; dy < 32; dy += 8) {
        const int y = by + dy, x = bx + tx;
        float v = V[(z * 512 + y) * 512 + x];
        float s, c;
        __sincosf(v, &s, &c);
        float2 t = make_float2(c, s);
        g_trow[(z * 512 + y) * 512 + x] = t;
        tile[dy][tx] = t;
    }
    __syncthreads();
#pragma unroll
    for (int dx = ty; dx < 32; dx += 8) {
        const int x = bx + dx, y = by + tx;
        g_tcol[(z * 512 + x) * 512 + y] = tile[tx][dx];
    }
}

// ------------------------------- main kernel --------------------------------
__global__ void __launch_bounds__(512, 1)
msp_main(const float* __restrict__ pre,
         const float* __restrict__ pim,
         const int*   __restrict__ ipos)
{
    extern __shared__ u64 smem[];
    u64* sR2 = smem;                 // pair-packed Re: [pair q][c]
    u64* sI2 = smem + 64 * PITCH2;   // pair-packed Im

    const int bid = blockIdx.x;
    const int k   = bid & 255;
    const int m   = bid >> 8;

    int py, px;
    {
        bool i64 = (ipos[1] | ipos[3] | ipos[5] | ipos[7] |
                    ipos[9] | ipos[11] | ipos[13] | ipos[15]) == 0;
        if (i64) { py = ipos[4 * k];  px = ipos[4 * k + 2]; }
        else     { py = ipos[2 * k];  px = ipos[2 * k + 1]; }
    }

    const int tid = threadIdx.x;
    const int l   = tid & 31;
    const int w   = tid >> 5;        // 16 warps
    const int l16 = l & 15;
    const int h   = l >> 4;
    const int baseLine = 2 * (w & 3) + 8 * h + 16 * ((w >> 2) & 1) + 32 * (w >> 3);

    Tw4 T;
    {
        T.owr[0] = 1.0f;  T.owi[0] = 0.0f;
#pragma unroll
        for (int t = 1; t < 8; t++) {
            float s, c; sincospif((float)(l16 * t) * (1.0f / 64.0f), &s, &c);
            T.owr[t] = c;  T.owi[t] = -s;
        }
        T.K = pk(RSQRT2, RSQRT2);
        { float s, c; sincospif((float)(8 * (l16 & 7)) * (1.0f / 64.0f), &s, &c);
          float tr = (l16 & 8) ? c : 1.0f, ti = (l16 & 8) ? -s : 0.0f;
          T.c8r = pk(tr, tr);  T.c8i = pk(ti, ti); }
        { float s, c; sincospif((float)(16 * (l16 & 3)) * (1.0f / 64.0f), &s, &c);
          float tr = (l16 & 4) ? c : 1.0f, ti = (l16 & 4) ? -s : 0.0f;
          T.c4r = pk(tr, tr);  T.c4i = pk(ti, ti); }
        T.p3 = ((l16 & 3) == 3);
        float s8 = (l16 & 8) ? -1.0f : 1.0f;  T.sg8 = pk(s8, s8);
        float s4 = (l16 & 4) ? -1.0f : 1.0f;  T.sg4 = pk(s4, s4);
        float s2 = (l16 & 2) ? -1.0f : 1.0f;  T.sg2 = pk(s2, s2);
        float s1 = (l16 & 1) ? -1.0f : 1.0f;  T.sg1 = pk(s1, s1);
    }

    // Fresnel factors (bitrev positions, 1/128 folded), then fused-span1 A/B
    float Ar[8], Ai[8], Br[8], Bi[8];
    {
        float Hr[8], Hi[8];
#pragma unroll
        for (int j = 0; j < 8; j++) {
            int idx = l16 + 16 * j;
            int fb  = (int)(__brev((unsigned)idx) >> 25);
            float f = (float)(fb < 64 ? fb : fb - 128) * (1.0f / 25.6f);
            float s, c;
            sincospif(-0.25f * f * f, &s, &c);      // lambda*dz = 0.25
            Hr[j] = c * (1.0f / 128.0f);
            Hi[j] = s * (1.0f / 128.0f);
        }
        const float sg1f = (l16 & 1) ? -1.0f : 1.0f;
#pragma unroll
        for (int j = 0; j < 8; j++) {
            float Hpr = __shfl_xor_sync(0xffffffffu, Hr[j], 1);
            float Hpi = __shfl_xor_sync(0xffffffffu, Hi[j], 1);
            Ar[j] = Hr[j] + Hpr;
            Ai[j] = Hi[j] + Hpi;
            Br[j] = sg1f * (Hr[j] - Hpr);
            Bi[j] = sg1f * (Hi[j] - Hpi);
        }
    }

    const float* prm  = pre + m * 16384;
    const float* pimm = pim + m * 16384;

#pragma unroll 1
    for (int pass = 0; pass < 9; pass++) {
        const bool rows = (pass & 1) == 0;
#pragma unroll 1
        for (int p = 0; p < 2; p++) {
            const int lineA = baseLine + 64 * p, lineB = lineA + 1;
            const int q = lineA >> 1;               // pair index (rows passes)
            u64 R[8], I[8];

            // ---- load ----
            if (pass == 0) {
#pragma unroll
                for (int j = 0; j < 8; j++) {
                    const int c = l16 + 16 * j;
                    R[j] = pk(prm[lineA * 128 + c],  prm[lineB * 128 + c]);
                    I[j] = pk(pimm[lineA * 128 + c], pimm[lineB * 128 + c]);
                }
            } else if (rows) {
#pragma unroll
                for (int j = 0; j < 8; j++) {
                    const int c = l16 + 16 * j;
                    R[j] = sR2[q * PITCH2 + c];
                    I[j] = sI2[q * PITCH2 + c];
                }
            } else {
                const int rb = l16 & 1;
#pragma unroll
                for (int j = 0; j < 8; j++) {
                    const int rq = (l16 >> 1) + 8 * j;
                    const float* fr = (const float*)(sR2 + rq * PITCH2 + lineA);
                    const float* fi = (const float*)(sI2 + rq * PITCH2 + lineA);
                    R[j] = pk(fr[rb], fr[rb + 2]);
                    I[j] = pk(fi[rb], fi[rb + 2]);
                }
            }

            // ---- pre-transmit (pass 0 only) ----
            if (pass == 0) {
                const float2* base = g_trow + py * 512 + px;
                transmit(R, I, base + lineA * 512, base + lineB * 512, l16);
            }

            if (pass <= 7) {
                dif8_head(R, I, T);
                fusedH(R, I, Ar, Ai, Br, Bi);
                dit8_tail(R, I, T);
            } else {
                dif8_head(R, I, T);
                span1(R, I, T.sg1);
            }

            // ---- mid-transmit + second FFT block ----
            if (pass >= 1 && pass <= 7) {
                const float2* base = rows
                    ? g_trow + (pass * 512 + py) * 512 + px
                    : g_tcol + (pass * 512 + px) * 512 + py;
                transmit(R, I, base + lineA * 512, base + lineB * 512, l16);
                if (pass <= 6) {
                    dif8_head(R, I, T);
                    fusedH(R, I, Ar, Ai, Br, Bi);
                    dit8_tail(R, I, T);
                } else {                    // pass 7: detector y-FFT only
                    dif8_head(R, I, T);
                    span1(R, I, T.sg1);
                }
            }

            // ---- store ----
            if (pass == 8) {
#pragma unroll
                for (int j = 0; j < 8; j++) {
                    const int c = l16 + 16 * j;
                    sR2[q * PITCH2 + c] = f2fma(R[j], R[j], f2mul(I[j], I[j]));
                }
            } else if (rows) {
#pragma unroll
                for (int j = 0; j < 8; j++) {
                    const int c = l16 + 16 * j;
                    sR2[q * PITCH2 + c] = R[j];
                    sI2[q * PITCH2 + c] = I[j];
                }
            } else {
                const int rb = l16 & 1;
#pragma unroll
                for (int j = 0; j < 8; j++) {
                    const int rq = (l16 >> 1) + 8 * j;
                    float* fr = (float*)(sR2 + rq * PITCH2 + lineA);
                    float* fi = (float*)(sI2 + rq * PITCH2 + lineA);
                    float a, b;
                    upk(R[j], a, b);  fr[rb] = a;  fr[rb + 2] = b;
                    upk(I[j], a, b);  fi[rb] = a;  fi[rb + 2] = b;
                }
            }
        }
        __syncthreads();
    }

    // bitrev permute |psi|^2 to natural order, vectorized STG.128
    {
        float4* out4 = (float4*)(g_int + ((size_t)bid << 14));
        for (int i = tid; i < 4096; i += 512) {
            const int y = i >> 5;
            const int qx = i & 31;
            const int ry = (int)(__brev((unsigned)y) >> 25);
            const int bx = (int)(__brev((unsigned)qx) >> 27);
            const float* row = (const float*)(sR2 + (ry >> 1) * PITCH2);
            const int cc = ry & 1;
            float4 v;
            v.x = row[2 * bx + cc];
            v.y = row[2 * (bx + 64) + cc];
            v.z = row[2 * (bx + 32) + cc];
            v.w = row[2 * (bx + 96) + cc];
            out4[i] = v;
        }
    }
}

// ------------------------------ finalize ------------------------------------
__global__ void msp_finalize(float* __restrict__ outp)
{
    const size_t i = ((size_t)blockIdx.x * blockDim.x + threadIdx.x) * 4;
    float4 a = *(const float4*)(g_int + i);
    float4 b = *(const float4*)(g_int + i + ((size_t)1 << 22));
    float4 c = *(const float4*)(g_int + i + ((size_t)2 << 22));
    float4 d = *(const float4*)(g_int + i + ((size_t)3 << 22));
    float4 o;
    o.x = sqrtf(1e-10f + (a.x + b.x + c.x + d.x) * (1.0f / 16384.0f));
    o.y = sqrtf(1e-10f + (a.y + b.y + c.y + d.y) * (1.0f / 16384.0f));
    o.z = sqrtf(1e-10f + (a.z + b.z + c.z + d.z) * (1.0f / 16384.0f));
    o.w = sqrtf(1e-10f + (a.w + b.w + c.w + d.w) * (1.0f / 16384.0f));
    *(float4*)(outp + i) = o;
}

// ------------------------------ launcher ------------------------------------
extern "C" void kernel_launch(void* const* d_in, const int* in_sizes, int n_in,
                              void* d_out, int out_size)
{
    const float* V   = (const float*)d_in[0];
    const float* pre = (const float*)d_in[1];
    const float* pim = (const float*)d_in[2];
    const int*   pos = (const int*)d_in[3];
    float* out = (float*)d_out;
    (void)in_sizes; (void)n_in; (void)out_size;

    msp_maketrans<<<dim3(16, 16, 8), dim3(32, 8)>>>(V);

    cudaFuncSetAttribute((const void*)msp_main,
                         cudaFuncAttributeMaxDynamicSharedMemorySize,
                         SMEM_BYTES);
    msp_main<<<1024, 512, SMEM_BYTES>>>(pre, pim, pos);
    msp_finalize<<<4096, 256>>>(out);
}